// round 16
// baseline (speedup 1.0000x reference)
#include <cuda_runtime.h>
#include <cuda_fp16.h>
#include <cstdint>
#include <math.h>

// N=4, S=4096, E=1024, H=16, D=64
// fused convert(x,W,bias) -> fp16 | ONE merged QKV GEMM [16384,3072] fp16-out
// | tensor-core head-gram attention (warp/position) | final GEMM fp32-out.
// R16 GEMM: CTA 128x128, 4 warps (64x64 warp tiles), 2 CTAs/SM, BK=64 with
// 3 stages (halves barrier count; bubble amortized over 128 MMAs/warp) and
// explicit ldmatrix double-buffering across the 4 k-steps of each K-tile.

// ---------------- scratch (alloc-guard compliant device globals) ----------
__device__ __half g_Xh[16777216];      // x in fp16
__device__ __half g_QKVh[50331648];    // QKV merged output [16384,3072] fp16
__device__ __half g_Oh[16777216];      // attn out, scrambled, fp16
__device__ __half g_Wh[4194304];       // Wq,Wk,Wv,Wo in fp16 (concat)
__device__ float  g_bias[3072];        // bq|bk|bv concat

__device__ __forceinline__ uint32_t smem_u32(const void* p) {
    uint32_t a;
    asm("{ .reg .u64 t; cvta.to.shared.u64 t, %1; cvt.u32.u64 %0, t; }"
        : "=r"(a) : "l"(p));
    return a;
}

#define LDMX4(r0, r1, r2, r3, addr) \
    asm volatile("ldmatrix.sync.aligned.m8n8.x4.shared.b16 {%0,%1,%2,%3}, [%4];" \
                 : "=r"(r0), "=r"(r1), "=r"(r2), "=r"(r3) : "r"(addr))
#define LDMX4T(r0, r1, r2, r3, addr) \
    asm volatile("ldmatrix.sync.aligned.m8n8.x4.trans.shared.b16 {%0,%1,%2,%3}, [%4];" \
                 : "=r"(r0), "=r"(r1), "=r"(r2), "=r"(r3) : "r"(addr))
#define MMA16816(acc, a0, a1, a2, a3, b0, b1) \
    asm volatile("mma.sync.aligned.m16n8k16.row.col.f32.f16.f16.f32 " \
                 "{%0,%1,%2,%3}, {%4,%5,%6,%7}, {%8,%9}, {%0,%1,%2,%3};" \
                 : "+f"((acc)[0]), "+f"((acc)[1]), "+f"((acc)[2]), "+f"((acc)[3]) \
                 : "r"(a0), "r"(a1), "r"(a2), "r"(a3), "r"(b0), "r"(b1))

// ---------------------------------------------------------------------------
// fp16 GEMM: C[16384,NC] = Ah[16384,1024] @ Bh[NC,1024]^T + bias (fp32 acc)
// CTA tile 128x128, 128 threads (4 warps, 2Mx2N of 64x64 warp tiles), BK=64,
// 3-stage cp.async pipeline (36KB/stage, pitch 144B), frag double-buffering
// across the 4 k-steps. Pitch 144B: 16B-aligned cp.async dsts, conflict-free
// ldmatrix (banks 4(r+c) mod 32 distinct over each 8-address phase).
// ---------------------------------------------------------------------------
static constexpr int GB_PITCH   = 144;
static constexpr int GB_A       = 128 * GB_PITCH;      // 18432
static constexpr int GB_STAGE_B = 256 * GB_PITCH;      // 36864
static constexpr int GH_SMEM    = 3 * GB_STAGE_B;      // 110592 (2 CTAs/SM)

template <typename OutT>
__global__ __launch_bounds__(128, 2)
void gemm_h(const __half* __restrict__ A, const __half* __restrict__ B,
            const float* __restrict__ bias, OutT* __restrict__ C, int ldc) {
    extern __shared__ __align__(128) char smem[];
    const uint32_t sb = smem_u32(smem);
    const int tid = threadIdx.x;
    const int warp = tid >> 5, lane = tid & 31;
    const int wm = (warp & 1) * 64;     // 2 warps along M
    const int wn = (warp >> 1) * 64;    // 2 warps along N

    const __half* Ab = A + (size_t)blockIdx.y * 128 * 1024;
    const __half* Bb = B + (size_t)blockIdx.x * 128 * 1024;

    float acc[4][8][4];
#pragma unroll
    for (int i = 0; i < 4; i++)
#pragma unroll
        for (int j = 0; j < 8; j++)
#pragma unroll
            for (int k = 0; k < 4; k++) acc[i][j][k] = 0.f;

    // stage v: A rows 0..127 (64 halfs = 128B data per row), then B rows
    auto load_stage = [&](int v) {
        const uint32_t base = sb + (uint32_t)(v % 3) * GB_STAGE_B;
        const int kb = v * 64;
#pragma unroll
        for (int i = 0; i < 8; i++) {            // A: 1024 16B-chunks
            const int c = tid + i * 128;
            const int row = c >> 3, ch = c & 7;
            const uint32_t da = base + (uint32_t)(row * GB_PITCH + ch * 16);
            asm volatile("cp.async.cg.shared.global [%0], [%1], 16;"
                         :: "r"(da), "l"(Ab + (size_t)row * 1024 + kb + ch * 8));
        }
#pragma unroll
        for (int i = 0; i < 8; i++) {            // B: 1024 16B-chunks
            const int c = tid + i * 128;
            const int row = c >> 3, ch = c & 7;
            const uint32_t db = base + GB_A + (uint32_t)(row * GB_PITCH + ch * 16);
            asm volatile("cp.async.cg.shared.global [%0], [%1], 16;"
                         :: "r"(db), "l"(Bb + (size_t)row * 1024 + kb + ch * 8));
        }
    };

    load_stage(0); asm volatile("cp.async.commit_group;");
    load_stage(1); asm volatile("cp.async.commit_group;");

    // ldmatrix per-lane address components (pitch 144)
    const int arow = (lane & 15) * GB_PITCH;          // A rows m0..m0+15
    const int asel = (lane >> 4) * 16;                // A: k or k+8 (bytes)
    const int brow = ((lane & 7) + ((lane >> 4) & 1) * 8) * GB_PITCH;  // B rows
    const int bsel = ((lane >> 3) & 1) * 16;          // B: k or k+8 (bytes)

    uint32_t af[2][4][4], bf[2][8][2];

    for (int kt = 0; kt < 16; kt++) {
        asm volatile("cp.async.wait_group 1;");
        __syncthreads();                  // stage kt resident; kt-1 consumed
        if (kt + 2 < 16) load_stage(kt + 2);
        asm volatile("cp.async.commit_group;");

        const uint32_t Abase = sb + (uint32_t)(kt % 3) * GB_STAGE_B;
        const uint32_t Bbase = Abase + GB_A;

        auto ldfrag = [&](int ks, int buf) {
            const int k0b = ks * 32;      // 16 halfs = 32 bytes
#pragma unroll
            for (int am = 0; am < 4; am++) {
                const uint32_t ad = Abase +
                    (uint32_t)((wm + am * 16) * GB_PITCH + arow + k0b + asel);
                LDMX4(af[buf][am][0], af[buf][am][1],
                      af[buf][am][2], af[buf][am][3], ad);
            }
#pragma unroll
            for (int g = 0; g < 4; g++) {
                const uint32_t bd = Bbase +
                    (uint32_t)((wn + g * 16) * GB_PITCH + brow + k0b + bsel);
                uint32_t r0, r1, r2, r3;
                LDMX4(r0, r1, r2, r3, bd);
                bf[buf][2 * g][0] = r0;     bf[buf][2 * g][1] = r1;
                bf[buf][2 * g + 1][0] = r2; bf[buf][2 * g + 1][1] = r3;
            }
        };

        ldfrag(0, 0);
#pragma unroll
        for (int ks = 0; ks < 4; ks++) {
            const int cur = ks & 1;
            if (ks < 3) ldfrag(ks + 1, cur ^ 1);
#pragma unroll
            for (int am = 0; am < 4; am++)
#pragma unroll
                for (int bn = 0; bn < 8; bn++)
                    MMA16816(acc[am][bn],
                             af[cur][am][0], af[cur][am][1],
                             af[cur][am][2], af[cur][am][3],
                             bf[cur][bn][0], bf[cur][bn][1]);
        }
    }

    // epilogue: bias add + stores (fp32 or fp16 out)
    const int rowBase = blockIdx.y * 128 + wm + (lane >> 2);
    const int colBase = blockIdx.x * 128 + wn;
#pragma unroll
    for (int bn = 0; bn < 8; bn++) {
        const int col = colBase + bn * 8 + (lane & 3) * 2;
        const float b0 = bias[col];
        const float b1 = bias[col + 1];
#pragma unroll
        for (int am = 0; am < 4; am++) {
            const int row = rowBase + am * 16;
            if constexpr (sizeof(OutT) == 4) {
                float2 v;
                v.x = acc[am][bn][0] + b0;
                v.y = acc[am][bn][1] + b1;
                *(float2*)&C[(size_t)row * ldc + col] = v;
                v.x = acc[am][bn][2] + b0;
                v.y = acc[am][bn][3] + b1;
                *(float2*)&C[(size_t)(row + 8) * ldc + col] = v;
            } else {
                __half2 h;
                h = __floats2half2_rn(acc[am][bn][0] + b0, acc[am][bn][1] + b1);
                *(__half2*)&C[(size_t)row * ldc + col] = h;
                h = __floats2half2_rn(acc[am][bn][2] + b0, acc[am][bn][3] + b1);
                *(__half2*)&C[(size_t)(row + 8) * ldc + col] = h;
            }
        }
    }
}

// ---------------------------------------------------------------------------
// Tensor-core head-gram attention: ONE WARP PER POSITION (unchanged, ~25us).
// QKV staged to warp-private smem (pitch 144B, conflict-free ldmatrix); gram
// via 8 HMMA; softmax on C frags via quad shuffles; P packed directly C->A
// fragment; out = P@V via ldmatrix.x4.trans + 8 HMMA. Store folds the
// reference's scrambled flat reshape: row' = q*256 + s/16, col' =
// (s%16)*64 + d. No __syncthreads anywhere.
// ---------------------------------------------------------------------------
static constexpr int ATT_WB   = 48 * 144;           // 6912 B per warp
static constexpr int ATT_SMEM = 8 * ATT_WB;         // 55296 B per block

__global__ __launch_bounds__(256)
void attn_mma() {
    extern __shared__ __align__(128) char asmem[];
    const int warpId = threadIdx.x >> 5;
    const int lane = threadIdx.x & 31;
    const int pos = blockIdx.x * 8 + warpId;
    const int s = pos & 4095;
    const int n = pos >> 12;

    const uint32_t wb = smem_u32(asmem) + (uint32_t)warpId * ATT_WB;
    const __half* src = g_QKVh + (size_t)pos * 3072;

    // stage 48 rows (Q:0-15, K:16-31, V:32-47), 64 halfs each, pitch 144B
#pragma unroll
    for (int it = 0; it < 12; it++) {
        const int id = it * 32 + lane;          // 0..383
        const int rr = id >> 3, cc = id & 7;
        const uint32_t dst = wb + (uint32_t)(rr * 144 + cc * 16);
        asm volatile("cp.async.cg.shared.global [%0], [%1], 16;"
                     :: "r"(dst), "l"(src + rr * 64 + cc * 8));
    }
    asm volatile("cp.async.commit_group;");
    asm volatile("cp.async.wait_group 0;");
    __syncwarp();

    const uint32_t Qb = wb;
    const uint32_t Kb = wb + 16 * 144;
    const uint32_t Vb = wb + 32 * 144;

    // ---- gram: C[2][4] covers 16x16 scores (2 n-octs) ----
    float c0[4] = {0.f, 0.f, 0.f, 0.f};
    float c1[4] = {0.f, 0.f, 0.f, 0.f};
    const uint32_t aAddr = Qb + (uint32_t)((lane & 15) * 144 + (lane >> 4) * 16);
    const uint32_t bAddr = Kb + (uint32_t)(((lane & 7) + ((lane >> 4) << 3)) * 144
                                           + ((lane >> 3) & 1) * 16);
#pragma unroll
    for (int kk = 0; kk < 4; kk++) {
        uint32_t a0, a1, a2, a3, m0, m1, m2, m3;
        LDMX4(a0, a1, a2, a3, aAddr + kk * 32);
        LDMX4(m0, m1, m2, m3, bAddr + kk * 32);
        MMA16816(c0, a0, a1, a2, a3, m0, m1);
        MMA16816(c1, a0, a1, a2, a3, m2, m3);
    }

    // ---- softmax on fragments (rows r = lane>>2 and r+8) ----
    float r0v[4] = {c0[0] * 0.125f, c0[1] * 0.125f, c1[0] * 0.125f, c1[1] * 0.125f};
    float r1v[4] = {c0[2] * 0.125f, c0[3] * 0.125f, c1[2] * 0.125f, c1[3] * 0.125f};
    float mx0 = fmaxf(fmaxf(r0v[0], r0v[1]), fmaxf(r0v[2], r0v[3]));
    float mx1 = fmaxf(fmaxf(r1v[0], r1v[1]), fmaxf(r1v[2], r1v[3]));
    mx0 = fmaxf(mx0, __shfl_xor_sync(0xffffffffu, mx0, 1));
    mx0 = fmaxf(mx0, __shfl_xor_sync(0xffffffffu, mx0, 2));
    mx1 = fmaxf(mx1, __shfl_xor_sync(0xffffffffu, mx1, 1));
    mx1 = fmaxf(mx1, __shfl_xor_sync(0xffffffffu, mx1, 2));
    float s0 = 0.f, s1 = 0.f;
#pragma unroll
    for (int i = 0; i < 4; i++) {
        r0v[i] = __expf(r0v[i] - mx0); s0 += r0v[i];
        r1v[i] = __expf(r1v[i] - mx1); s1 += r1v[i];
    }
    s0 += __shfl_xor_sync(0xffffffffu, s0, 1);
    s0 += __shfl_xor_sync(0xffffffffu, s0, 2);
    s1 += __shfl_xor_sync(0xffffffffu, s1, 1);
    s1 += __shfl_xor_sync(0xffffffffu, s1, 2);
    const float inv0 = 1.0f / s0, inv1 = 1.0f / s1;

    // ---- pack P to fp16 A-frags (direct C->A layout identity) ----
    __half2 pa0 = __floats2half2_rn(r0v[0] * inv0, r0v[1] * inv0);
    __half2 pa1 = __floats2half2_rn(r1v[0] * inv1, r1v[1] * inv1);
    __half2 pa2 = __floats2half2_rn(r0v[2] * inv0, r0v[3] * inv0);
    __half2 pa3 = __floats2half2_rn(r1v[2] * inv1, r1v[3] * inv1);
    const uint32_t p0 = *(uint32_t*)&pa0, p1 = *(uint32_t*)&pa1;
    const uint32_t p2 = *(uint32_t*)&pa2, p3 = *(uint32_t*)&pa3;

    // ---- out = P @ V : 8 n-chunks of 8 cols ----
    float o[8][4];
#pragma unroll
    for (int ch = 0; ch < 8; ch++)
#pragma unroll
        for (int k = 0; k < 4; k++) o[ch][k] = 0.f;
    const uint32_t vAddr = Vb + (uint32_t)((lane & 15) * 144 + (lane >> 4) * 16);
#pragma unroll
    for (int i = 0; i < 4; i++) {
        uint32_t m0, m1, m2, m3;
        LDMX4T(m0, m1, m2, m3, vAddr + i * 32);
        MMA16816(o[2 * i],     p0, p1, p2, p3, m0, m1);
        MMA16816(o[2 * i + 1], p0, p1, p2, p3, m2, m3);
    }

    // ---- scrambled store, fp16 ----
    const int r = lane >> 2, c2 = (lane & 3) * 2;
    const size_t base2 = (((size_t)n << 12) + (size_t)(s >> 4)) * 1024
                       + (size_t)(s & 15) * 64;
#pragma unroll
    for (int ch = 0; ch < 8; ch++) {
        const int d = ch * 8 + c2;
        __half2 lo = __floats2half2_rn(o[ch][0], o[ch][1]);
        __half2 hi = __floats2half2_rn(o[ch][2], o[ch][3]);
        *(__half2*)&g_Oh[base2 + (size_t)r * 262144 + d] = lo;
        *(__half2*)&g_Oh[base2 + (size_t)(r + 8) * 262144 + d] = hi;
    }
}

// ---------------- fused conversion: x + 4 weights + bias concat ------------
__global__ __launch_bounds__(256)
void conv_fused(const float4* __restrict__ x,
                const float4* __restrict__ wq, const float4* __restrict__ wk,
                const float4* __restrict__ wv, const float4* __restrict__ wo,
                const float4* __restrict__ bq, const float4* __restrict__ bk,
                const float4* __restrict__ bv) {
    const int i = blockIdx.x * 256 + threadIdx.x;
    float4 v;
    uint2* dst;
    if (i < 4194304) {
        v = x[i];
        dst = (uint2*)g_Xh + i;
    } else {
        const int w = i - 4194304;           // 0..1048575
        const int seg = w >> 18;             // 0..3
        const int off = w & 262143;
        v = (seg == 0) ? wq[off] : (seg == 1) ? wk[off]
          : (seg == 2) ? wv[off] : wo[off];
        dst = (uint2*)g_Wh + w;
    }
    __half2 h0 = __floats2half2_rn(v.x, v.y);
    __half2 h1 = __floats2half2_rn(v.z, v.w);
    uint2 o;
    o.x = *(uint32_t*)&h0;
    o.y = *(uint32_t*)&h1;
    *dst = o;

    if (i < 768) {  // bias concat (3072 floats = 768 float4)
        float4 b = (i < 256) ? bq[i] : (i < 512) ? bk[i - 256] : bv[i - 512];
        ((float4*)g_bias)[i] = b;
    }
}

// ---------------- launch ---------------------------------------------------
extern "C" void kernel_launch(void* const* d_in, const int* in_sizes, int n_in,
                              void* d_out, int out_size) {
    const float* x  = (const float*)d_in[0];
    const float* Wq = (const float*)d_in[1];
    const float* bq = (const float*)d_in[2];
    const float* Wk = (const float*)d_in[3];
    const float* bk = (const float*)d_in[4];
    const float* Wv = (const float*)d_in[5];
    const float* bv = (const float*)d_in[6];
    const float* Wo = (const float*)d_in[7];
    const float* bo = (const float*)d_in[8];

    __half *pXh, *pWh, *pOh, *pQKV;
    float *pBias;
    cudaGetSymbolAddress((void**)&pXh,  g_Xh);
    cudaGetSymbolAddress((void**)&pWh,  g_Wh);
    cudaGetSymbolAddress((void**)&pOh,  g_Oh);
    cudaGetSymbolAddress((void**)&pQKV, g_QKVh);
    cudaGetSymbolAddress((void**)&pBias, g_bias);

    cudaFuncSetAttribute(gemm_h<__half>,
                         cudaFuncAttributeMaxDynamicSharedMemorySize, GH_SMEM);
    cudaFuncSetAttribute(gemm_h<float>,
                         cudaFuncAttributeMaxDynamicSharedMemorySize, GH_SMEM);
    cudaFuncSetAttribute(attn_mma,
                         cudaFuncAttributeMaxDynamicSharedMemorySize, ATT_SMEM);

    conv_fused<<<20480, 256>>>((const float4*)x,
                               (const float4*)Wq, (const float4*)Wk,
                               (const float4*)Wv, (const float4*)Wo,
                               (const float4*)bq, (const float4*)bk,
                               (const float4*)bv);

    // merged QKV GEMM: C[16384,3072] fp16
    gemm_h<__half><<<dim3(24, 128), 128, GH_SMEM>>>(pXh, pWh, pBias, pQKV, 3072);
    attn_mma<<<2048, 256, ATT_SMEM>>>();
    // final GEMM: fp32 out
    gemm_h<float><<<dim3(8, 128), 128, GH_SMEM>>>(pOh, pWh + 3145728, bo,
                                                  (float*)d_out, 1024);
}

// round 17
// speedup vs baseline: 1.0509x; 1.0509x over previous
#include <cuda_runtime.h>
#include <cuda_fp16.h>
#include <cstdint>
#include <math.h>

// N=4, S=4096, E=1024, H=16, D=64
// fused convert(x,W,bias) -> fp16 | ONE merged QKV GEMM [16384,3072] fp16-out
// | tensor-core head-gram attention (warp/position) | final GEMM fp32-out.
// R17: GEMM mainloop reverted EXACTLY to R15 (436us best: CTA 128x128,
// 4 warps of 64x64, 2 CTAs/SM, BK=32, 4-stage). New: attention and the
// final GEMM are split into 4 batch-chunks on two streams so attn(b+1)
// (DRAM-bound) overlaps final(b) (tensor-bound); the scramble keeps batch
// n's attn output inside final-GEMM rows [n*4096,(n+1)*4096) so chunks are
// independent. Streams/events created per call (no statics, no dev alloc).

// ---------------- scratch (alloc-guard compliant device globals) ----------
__device__ __half g_Xh[16777216];      // x in fp16
__device__ __half g_QKVh[50331648];    // QKV merged output [16384,3072] fp16
__device__ __half g_Oh[16777216];      // attn out, scrambled, fp16
__device__ __half g_Wh[4194304];       // Wq,Wk,Wv,Wo in fp16 (concat)
__device__ float  g_bias[3072];        // bq|bk|bv concat

__device__ __forceinline__ uint32_t smem_u32(const void* p) {
    uint32_t a;
    asm("{ .reg .u64 t; cvta.to.shared.u64 t, %1; cvt.u32.u64 %0, t; }"
        : "=r"(a) : "l"(p));
    return a;
}

#define LDMX4(r0, r1, r2, r3, addr) \
    asm volatile("ldmatrix.sync.aligned.m8n8.x4.shared.b16 {%0,%1,%2,%3}, [%4];" \
                 : "=r"(r0), "=r"(r1), "=r"(r2), "=r"(r3) : "r"(addr))
#define LDMX4T(r0, r1, r2, r3, addr) \
    asm volatile("ldmatrix.sync.aligned.m8n8.x4.trans.shared.b16 {%0,%1,%2,%3}, [%4];" \
                 : "=r"(r0), "=r"(r1), "=r"(r2), "=r"(r3) : "r"(addr))
#define MMA16816(acc, a0, a1, a2, a3, b0, b1) \
    asm volatile("mma.sync.aligned.m16n8k16.row.col.f32.f16.f16.f32 " \
                 "{%0,%1,%2,%3}, {%4,%5,%6,%7}, {%8,%9}, {%0,%1,%2,%3};" \
                 : "+f"((acc)[0]), "+f"((acc)[1]), "+f"((acc)[2]), "+f"((acc)[3]) \
                 : "r"(a0), "r"(a1), "r"(a2), "r"(a3), "r"(b0), "r"(b1))

// ---------------------------------------------------------------------------
// fp16 GEMM (R15 config): C[M,NC] = A[M,1024] @ B[NC,1024]^T + bias (fp32 acc)
// CTA tile 128x128, 128 threads (4 warps, 2Mx2N of 64x64 warp tiles), BK=32,
// 4-stage cp.async pipeline. smem row pitch 80B: 16B-aligned cp.async dsts
// AND conflict-free ldmatrix (banks (20r+c) mod 32 cover all 32).
// ---------------------------------------------------------------------------
static constexpr int GH_A_B     = 10240;           // 128 rows * 80B
static constexpr int GH_STAGE_B = 20480;           // (128 A + 128 B) * 80B
static constexpr int GH_SMEM    = 4 * GH_STAGE_B;  // 81920 per CTA (2 CTAs/SM)

template <typename OutT>
__global__ __launch_bounds__(128, 2)
void gemm_h(const __half* __restrict__ A, const __half* __restrict__ B,
            const float* __restrict__ bias, OutT* __restrict__ C, int ldc) {
    extern __shared__ __align__(128) char smem[];
    const uint32_t sb = smem_u32(smem);
    const int tid = threadIdx.x;
    const int warp = tid >> 5, lane = tid & 31;
    const int wm = (warp & 1) * 64;     // 2 warps along M
    const int wn = (warp >> 1) * 64;    // 2 warps along N

    const __half* Ab = A + (size_t)blockIdx.y * 128 * 1024;
    const __half* Bb = B + (size_t)blockIdx.x * 128 * 1024;

    float acc[4][8][4];
#pragma unroll
    for (int i = 0; i < 4; i++)
#pragma unroll
        for (int j = 0; j < 8; j++)
#pragma unroll
            for (int k = 0; k < 4; k++) acc[i][j][k] = 0.f;

    auto load_stage = [&](int v) {
        const uint32_t base = sb + (uint32_t)(v & 3) * GH_STAGE_B;
        const int kb = v * 32;
#pragma unroll
        for (int i = 0; i < 4; i++) {
            const int c = tid + i * 128;       // 0..511
            const int row = c >> 2, ch = c & 3;
            const uint32_t da = base + (uint32_t)(row * 80 + ch * 16);
            asm volatile("cp.async.cg.shared.global [%0], [%1], 16;"
                         :: "r"(da), "l"(Ab + (size_t)row * 1024 + kb + ch * 8));
        }
#pragma unroll
        for (int i = 0; i < 4; i++) {
            const int c = tid + i * 128;       // 0..511
            const int row = c >> 2, ch = c & 3;
            const uint32_t db = base + GH_A_B + (uint32_t)(row * 80 + ch * 16);
            asm volatile("cp.async.cg.shared.global [%0], [%1], 16;"
                         :: "r"(db), "l"(Bb + (size_t)row * 1024 + kb + ch * 8));
        }
    };

    load_stage(0); asm volatile("cp.async.commit_group;");
    load_stage(1); asm volatile("cp.async.commit_group;");
    load_stage(2); asm volatile("cp.async.commit_group;");

    // ldmatrix per-lane address components
    const int arow80 = (lane & 15) * 80;            // A rows m0..m0+15
    const int asel   = (lane >> 4) * 16;            // A: k or k+8 (bytes)
    const int brow80 = ((lane & 7) + ((lane >> 4) & 1) * 8) * 80;  // B rows n
    const int bsel   = ((lane >> 3) & 1) * 16;      // B: k or k+8 (bytes)

    for (int kt = 0; kt < 32; kt++) {
        asm volatile("cp.async.wait_group 2;");
        __syncthreads();                  // stage kt resident for all threads
        if (kt + 3 < 32) load_stage(kt + 3);
        asm volatile("cp.async.commit_group;");

        const uint32_t Abase = sb + (uint32_t)(kt & 3) * GH_STAGE_B;
        const uint32_t Bbase = Abase + GH_A_B;
#pragma unroll
        for (int ks = 0; ks < 2; ks++) {
            const int k0b = ks * 32;      // 16 halfs = 32 bytes
            uint32_t a[4][4];
#pragma unroll
            for (int am = 0; am < 4; am++) {
                const uint32_t ad = Abase +
                    (uint32_t)((wm + am * 16) * 80 + arow80 + k0b + asel);
                LDMX4(a[am][0], a[am][1], a[am][2], a[am][3], ad);
            }
            uint32_t b[8][2];
#pragma unroll
            for (int g = 0; g < 4; g++) {
                const uint32_t bd = Bbase +
                    (uint32_t)((wn + g * 16) * 80 + brow80 + k0b + bsel);
                uint32_t r0, r1, r2, r3;
                LDMX4(r0, r1, r2, r3, bd);
                b[2 * g][0] = r0; b[2 * g][1] = r1;
                b[2 * g + 1][0] = r2; b[2 * g + 1][1] = r3;
            }
#pragma unroll
            for (int am = 0; am < 4; am++)
#pragma unroll
                for (int bn = 0; bn < 8; bn++)
                    MMA16816(acc[am][bn], a[am][0], a[am][1], a[am][2], a[am][3],
                             b[bn][0], b[bn][1]);
        }
    }

    // epilogue: bias add + stores (fp32 or fp16 out)
    const int rowBase = blockIdx.y * 128 + wm + (lane >> 2);
    const int colBase = blockIdx.x * 128 + wn;
#pragma unroll
    for (int bn = 0; bn < 8; bn++) {
        const int col = colBase + bn * 8 + (lane & 3) * 2;
        const float b0 = bias[col];
        const float b1 = bias[col + 1];
#pragma unroll
        for (int am = 0; am < 4; am++) {
            const int row = rowBase + am * 16;
            if constexpr (sizeof(OutT) == 4) {
                float2 v;
                v.x = acc[am][bn][0] + b0;
                v.y = acc[am][bn][1] + b1;
                *(float2*)&C[(size_t)row * ldc + col] = v;
                v.x = acc[am][bn][2] + b0;
                v.y = acc[am][bn][3] + b1;
                *(float2*)&C[(size_t)(row + 8) * ldc + col] = v;
            } else {
                __half2 h;
                h = __floats2half2_rn(acc[am][bn][0] + b0, acc[am][bn][1] + b1);
                *(__half2*)&C[(size_t)row * ldc + col] = h;
                h = __floats2half2_rn(acc[am][bn][2] + b0, acc[am][bn][3] + b1);
                *(__half2*)&C[(size_t)(row + 8) * ldc + col] = h;
            }
        }
    }
}

// ---------------------------------------------------------------------------
// Tensor-core head-gram attention: ONE WARP PER POSITION (R14/R15, ~25us
// total; here launched in 4 batch-chunks of 4096 positions). posBase selects
// the chunk. Store folds the reference's scrambled flat reshape:
// row' = n*4096 + q*256 + s/16, col' = (s%16)*64 + d. No __syncthreads.
// ---------------------------------------------------------------------------
static constexpr int ATT_WB   = 48 * 144;           // 6912 B per warp
static constexpr int ATT_SMEM = 8 * ATT_WB;         // 55296 B per block

__global__ __launch_bounds__(256)
void attn_mma(int posBase) {
    extern __shared__ __align__(128) char asmem[];
    const int warpId = threadIdx.x >> 5;
    const int lane = threadIdx.x & 31;
    const int pos = posBase + blockIdx.x * 8 + warpId;
    const int s = pos & 4095;
    const int n = pos >> 12;

    const uint32_t wb = smem_u32(asmem) + (uint32_t)warpId * ATT_WB;
    const __half* src = g_QKVh + (size_t)pos * 3072;

    // stage 48 rows (Q:0-15, K:16-31, V:32-47), 64 halfs each, pitch 144B
#pragma unroll
    for (int it = 0; it < 12; it++) {
        const int id = it * 32 + lane;          // 0..383
        const int rr = id >> 3, cc = id & 7;
        const uint32_t dst = wb + (uint32_t)(rr * 144 + cc * 16);
        asm volatile("cp.async.cg.shared.global [%0], [%1], 16;"
                     :: "r"(dst), "l"(src + rr * 64 + cc * 8));
    }
    asm volatile("cp.async.commit_group;");
    asm volatile("cp.async.wait_group 0;");
    __syncwarp();

    const uint32_t Qb = wb;
    const uint32_t Kb = wb + 16 * 144;
    const uint32_t Vb = wb + 32 * 144;

    // ---- gram: C[2][4] covers 16x16 scores (2 n-octs) ----
    float c0[4] = {0.f, 0.f, 0.f, 0.f};
    float c1[4] = {0.f, 0.f, 0.f, 0.f};
    const uint32_t aAddr = Qb + (uint32_t)((lane & 15) * 144 + (lane >> 4) * 16);
    const uint32_t bAddr = Kb + (uint32_t)(((lane & 7) + ((lane >> 4) << 3)) * 144
                                           + ((lane >> 3) & 1) * 16);
#pragma unroll
    for (int kk = 0; kk < 4; kk++) {
        uint32_t a0, a1, a2, a3, m0, m1, m2, m3;
        LDMX4(a0, a1, a2, a3, aAddr + kk * 32);
        LDMX4(m0, m1, m2, m3, bAddr + kk * 32);
        MMA16816(c0, a0, a1, a2, a3, m0, m1);
        MMA16816(c1, a0, a1, a2, a3, m2, m3);
    }

    // ---- softmax on fragments (rows r = lane>>2 and r+8) ----
    float r0v[4] = {c0[0] * 0.125f, c0[1] * 0.125f, c1[0] * 0.125f, c1[1] * 0.125f};
    float r1v[4] = {c0[2] * 0.125f, c0[3] * 0.125f, c1[2] * 0.125f, c1[3] * 0.125f};
    float mx0 = fmaxf(fmaxf(r0v[0], r0v[1]), fmaxf(r0v[2], r0v[3]));
    float mx1 = fmaxf(fmaxf(r1v[0], r1v[1]), fmaxf(r1v[2], r1v[3]));
    mx0 = fmaxf(mx0, __shfl_xor_sync(0xffffffffu, mx0, 1));
    mx0 = fmaxf(mx0, __shfl_xor_sync(0xffffffffu, mx0, 2));
    mx1 = fmaxf(mx1, __shfl_xor_sync(0xffffffffu, mx1, 1));
    mx1 = fmaxf(mx1, __shfl_xor_sync(0xffffffffu, mx1, 2));
    float s0 = 0.f, s1 = 0.f;
#pragma unroll
    for (int i = 0; i < 4; i++) {
        r0v[i] = __expf(r0v[i] - mx0); s0 += r0v[i];
        r1v[i] = __expf(r1v[i] - mx1); s1 += r1v[i];
    }
    s0 += __shfl_xor_sync(0xffffffffu, s0, 1);
    s0 += __shfl_xor_sync(0xffffffffu, s0, 2);
    s1 += __shfl_xor_sync(0xffffffffu, s1, 1);
    s1 += __shfl_xor_sync(0xffffffffu, s1, 2);
    const float inv0 = 1.0f / s0, inv1 = 1.0f / s1;

    // ---- pack P to fp16 A-frags (direct C->A layout identity) ----
    __half2 pa0 = __floats2half2_rn(r0v[0] * inv0, r0v[1] * inv0);
    __half2 pa1 = __floats2half2_rn(r1v[0] * inv1, r1v[1] * inv1);
    __half2 pa2 = __floats2half2_rn(r0v[2] * inv0, r0v[3] * inv0);
    __half2 pa3 = __floats2half2_rn(r1v[2] * inv1, r1v[3] * inv1);
    const uint32_t p0 = *(uint32_t*)&pa0, p1 = *(uint32_t*)&pa1;
    const uint32_t p2 = *(uint32_t*)&pa2, p3 = *(uint32_t*)&pa3;

    // ---- out = P @ V : 8 n-chunks of 8 cols ----
    float o[8][4];
#pragma unroll
    for (int ch = 0; ch < 8; ch++)
#pragma unroll
        for (int k = 0; k < 4; k++) o[ch][k] = 0.f;
    const uint32_t vAddr = Vb + (uint32_t)((lane & 15) * 144 + (lane >> 4) * 16);
#pragma unroll
    for (int i = 0; i < 4; i++) {
        uint32_t m0, m1, m2, m3;
        LDMX4T(m0, m1, m2, m3, vAddr + i * 32);
        MMA16816(o[2 * i],     p0, p1, p2, p3, m0, m1);
        MMA16816(o[2 * i + 1], p0, p1, p2, p3, m2, m3);
    }

    // ---- scrambled store, fp16 ----
    const int r = lane >> 2, c2 = (lane & 3) * 2;
    const size_t base2 = (((size_t)n << 12) + (size_t)(s >> 4)) * 1024
                       + (size_t)(s & 15) * 64;
#pragma unroll
    for (int ch = 0; ch < 8; ch++) {
        const int d = ch * 8 + c2;
        __half2 lo = __floats2half2_rn(o[ch][0], o[ch][1]);
        __half2 hi = __floats2half2_rn(o[ch][2], o[ch][3]);
        *(__half2*)&g_Oh[base2 + (size_t)r * 262144 + d] = lo;
        *(__half2*)&g_Oh[base2 + (size_t)(r + 8) * 262144 + d] = hi;
    }
}

// ---------------- fused conversion: x + 4 weights + bias concat ------------
__global__ __launch_bounds__(256)
void conv_fused(const float4* __restrict__ x,
                const float4* __restrict__ wq, const float4* __restrict__ wk,
                const float4* __restrict__ wv, const float4* __restrict__ wo,
                const float4* __restrict__ bq, const float4* __restrict__ bk,
                const float4* __restrict__ bv) {
    const int i = blockIdx.x * 256 + threadIdx.x;
    float4 v;
    uint2* dst;
    if (i < 4194304) {
        v = x[i];
        dst = (uint2*)g_Xh + i;
    } else {
        const int w = i - 4194304;           // 0..1048575
        const int seg = w >> 18;             // 0..3
        const int off = w & 262143;
        v = (seg == 0) ? wq[off] : (seg == 1) ? wk[off]
          : (seg == 2) ? wv[off] : wo[off];
        dst = (uint2*)g_Wh + w;
    }
    __half2 h0 = __floats2half2_rn(v.x, v.y);
    __half2 h1 = __floats2half2_rn(v.z, v.w);
    uint2 o;
    o.x = *(uint32_t*)&h0;
    o.y = *(uint32_t*)&h1;
    *dst = o;

    if (i < 768) {  // bias concat (3072 floats = 768 float4)
        float4 b = (i < 256) ? bq[i] : (i < 512) ? bk[i - 256] : bv[i - 512];
        ((float4*)g_bias)[i] = b;
    }
}

// ---------------- launch ---------------------------------------------------
extern "C" void kernel_launch(void* const* d_in, const int* in_sizes, int n_in,
                              void* d_out, int out_size) {
    const float* x  = (const float*)d_in[0];
    const float* Wq = (const float*)d_in[1];
    const float* bq = (const float*)d_in[2];
    const float* Wk = (const float*)d_in[3];
    const float* bk = (const float*)d_in[4];
    const float* Wv = (const float*)d_in[5];
    const float* bv = (const float*)d_in[6];
    const float* Wo = (const float*)d_in[7];
    const float* bo = (const float*)d_in[8];

    __half *pXh, *pWh, *pOh, *pQKV;
    float *pBias;
    cudaGetSymbolAddress((void**)&pXh,  g_Xh);
    cudaGetSymbolAddress((void**)&pWh,  g_Wh);
    cudaGetSymbolAddress((void**)&pOh,  g_Oh);
    cudaGetSymbolAddress((void**)&pQKV, g_QKVh);
    cudaGetSymbolAddress((void**)&pBias, g_bias);

    cudaFuncSetAttribute(gemm_h<__half>,
                         cudaFuncAttributeMaxDynamicSharedMemorySize, GH_SMEM);
    cudaFuncSetAttribute(gemm_h<float>,
                         cudaFuncAttributeMaxDynamicSharedMemorySize, GH_SMEM);
    cudaFuncSetAttribute(attn_mma,
                         cudaFuncAttributeMaxDynamicSharedMemorySize, ATT_SMEM);

    // side stream + events, created fresh per call (kernel_launch runs only a
    // handful of times; no statics, no device allocations, intentionally not
    // destroyed so captured graph nodes stay valid).
    cudaStream_t s2;
    cudaStreamCreateWithFlags(&s2, cudaStreamNonBlocking);
    cudaEvent_t evQ, evA[4];
    cudaEventCreateWithFlags(&evQ, cudaEventDisableTiming);
    for (int b = 0; b < 4; b++)
        cudaEventCreateWithFlags(&evA[b], cudaEventDisableTiming);

    conv_fused<<<20480, 256>>>((const float4*)x,
                               (const float4*)Wq, (const float4*)Wk,
                               (const float4*)Wv, (const float4*)Wo,
                               (const float4*)bq, (const float4*)bk,
                               (const float4*)bv);

    // merged QKV GEMM: C[16384,3072] fp16 (single deep launch, 10.4 waves)
    gemm_h<__half><<<dim3(24, 128), 128, GH_SMEM>>>(pXh, pWh, pBias, pQKV, 3072);
    cudaEventRecord(evQ, 0);

    // attention in 4 batch-chunks on the side stream
    cudaStreamWaitEvent(s2, evQ, 0);
    for (int b = 0; b < 4; b++) {
        attn_mma<<<512, 256, ATT_SMEM, s2>>>(b * 4096);
        cudaEventRecord(evA[b], s2);
    }

    // final GEMM in 4 batch-chunks on the main stream; final(b) overlaps
    // attn(b+1) on s2. Each chunk covers d_out rows [b*4096,(b+1)*4096).
    for (int b = 0; b < 4; b++) {
        cudaStreamWaitEvent(0, evA[b], 0);
        gemm_h<float><<<dim3(8, 32), 128, GH_SMEM>>>(
            pOh + (size_t)b * 4194304, pWh + 3145728, bo,
            (float*)d_out + (size_t)b * 4194304, 1024);
    }
}